// round 17
// baseline (speedup 1.0000x reference)
#include <cuda_runtime.h>
#include <cuda_bf16.h>
#include <math.h>

#define SIZE   512
#define N_PHOS 256
#define H      10
#define THRESH 0.05f

#define MAX_OH 52        // disk span (<=31) + 2H + 1
#define MAX_TW 73        // MAX_OH + 2H (+1 pad)

#define STRIP_H 26
#define STRIPS  2
#define NTASKS  (N_PHOS * STRIPS)   // 512

#define NBLOCKS  128                 // one block per SM
#define NTHREADS 1024                // 2 x 512-thread worker halves
#define PX_PER_BLOCK ((SIZE * SIZE) / NBLOCKS)   // 2048 -> one float2 / thread

// Self-restoring scratch accumulator: zero at module load; phase D re-zeros
// it every run, so it is zero at every kernel entry (replay-deterministic).
__device__ __align__(16) float g_scratch[SIZE * SIZE];

// Per-phosphene prologue staging (written in B0, read by B1 tasks).
__device__ float    g_w  [N_PHOS][21];
__device__ float    g_cw [N_PHOS][22];
__device__ unsigned g_lohi[N_PHOS][MAX_TW];
__device__ int4     g_geoA[N_PHOS];     // oy0, ox0, cLo, tw
__device__ int4     g_geoB[N_PHOS];     // ow, oh, interior, scale-bits

__device__ int      g_max_bits  = 0;
__device__ unsigned g_bar_count = 0;
__device__ unsigned g_bar_gen   = 0;
__device__ unsigned g_task_ctr  = 0;    // reset after barrier 1 each run

static __device__ __forceinline__ int refl(int i) {
    if (i < 0)        i = -i;
    if (i > SIZE - 1) i = 2 * (SIZE - 1) - i;
    return i;
}

// Named barrier over one 512-thread half (ids 1,2).
#define GBAR(s) asm volatile("bar.sync %0, 512;" :: "r"((s) + 1) : "memory")

// Sense-reversing software grid barrier; 128 blocks, 1/SM, all co-resident.
static __device__ __forceinline__ void grid_barrier() {
    __syncthreads();
    if (threadIdx.x == 0) {
        unsigned my_gen = *((volatile unsigned*)&g_bar_gen);
        __threadfence();
        unsigned arrived = atomicAdd(&g_bar_count, 1u);
        if (arrived == NBLOCKS - 1) {
            atomicExch(&g_bar_count, 0u);
            __threadfence();
            atomicExch(&g_bar_gen, my_gen + 1u);
        } else {
            while (*((volatile unsigned*)&g_bar_gen) == my_gen) { __nanosleep(32); }
        }
        __threadfence();
    }
    __syncthreads();
}

// Interval sum of taps dy in [a,b] (clamped to [-H,H]) from prefix weights.
static __device__ __forceinline__ float ivsum(int a, int b, const float* __restrict__ cw2) {
    a = max(a, -H);
    b = min(b,  H);
    return (a <= b) ? (cw2[b + H + 1] - cw2[a + H]) : 0.0f;
}

__global__ __launch_bounds__(NTHREADS, 1) void k_fused(
    const float* __restrict__ phoscoding,
    const float* __restrict__ grid,
    float* __restrict__ img)
{
    const int tid = threadIdx.x;
    const int sub = tid >> 9;                    // 0/1: worker half
    const int l   = tid & 511;                   // lane within half

    __shared__ float    sw [2][21];
    __shared__ float    scw[2][22];
    __shared__ unsigned slh[2][MAX_TW];
    __shared__ float    t  [2][STRIP_H][MAX_TW];
    __shared__ unsigned s_task[2];
    __shared__ float    smax[32];

    if (blockIdx.x == 0 && tid == 0) g_max_bits = 0;

    // =============== B0: prologue for this half's own phosphene ===============
    {
        const int p0 = (blockIdx.x << 1) + sub;
        const float bright = phoscoding[p0];
        const float x = grid[3 * p0 + 0];
        const float y = grid[3 * p0 + 1];
        const float r = grid[3 * p0 + 2];

        const float sigma = r / 3.0f;
        const float half  = ceilf(2.0f * sigma);
        const float r2    = __fmul_rn(r, r);
        const float cx = x - 1.0f, cy = y - 1.0f;

        const int oy0 = max(0,        (int)floorf(cy - r) - H);
        const int oy1 = min(SIZE - 1, (int)ceilf (cy + r) + H);
        const int ox0 = max(0,        (int)floorf(cx - r) - H);
        const int ox1 = min(SIZE - 1, (int)ceilf (cx + r) + H);
        const int cLo = max(0,        ox0 - H);
        const int cHi = min(SIZE - 1, ox1 + H);

        int oh = oy1 - oy0 + 1;          // <= 52
        int ow = ox1 - ox0 + 1;          // <= 52
        int tw = cHi - cLo + 1;          // <= 72
        if (oh > MAX_OH) oh = MAX_OH;
        if (tw > MAX_TW) tw = MAX_TW;

        // Weights + prefix scan (warp 0 of the half), staged to global.
        if (l < 32) {
            float pos = (float)(l - H);
            float q   = pos / sigma;
            float v   = (l < 2 * H + 1 && fabsf(pos) <= half)
                        ? expf(-0.5f * (q * q)) : 0.0f;
            float s = v;
            #pragma unroll
            for (int off = 1; off < 32; off <<= 1) {
                float u = __shfl_up_sync(0xffffffffu, s, off);
                if (l >= off) s += u;
            }
            float wsum = __shfl_sync(0xffffffffu, s, 2 * H);
            if (l < 2 * H + 1) {
                g_w [p0][l]     = v;
                g_cw[p0][l + 1] = s;
            }
            if (l == 0) {
                g_cw[p0][0] = 0.0f;
                float scale = bright / (wsum * wsum);
                g_geoA[p0] = make_int4(oy0, ox0, cLo, tw);
                int interior = (ox0 >= H) && (ox1 <= SIZE - 1 - H);
                g_geoB[p0] = make_int4(ow, oh, interior, __float_as_int(scale));
            }
        }

        // Per-column disk row-interval [mLo, mHi], exact reference rounding:
        // rn(dx2 + rn(dyc*dyc)) <= rn(r*r).
        if (l < tw) {
            int   col = cLo + l;
            float dxc = (float)(col + 1) - x;
            float dx2 = __fmul_rn(dxc, dxc);
            int lo = 512, hi = -512;                 // empty sentinel
            if (dx2 <= r2) {
                float hy = sqrtf(fmaxf(r2 - dx2, 0.0f));
                lo = (int)ceilf (y - hy) - 1;
                hi = (int)floorf(y + hy) - 1;
                #pragma unroll
                for (int k = 0; k < 2; k++) {
                    float d = (float)(lo) - y;
                    if (__fadd_rn(dx2, __fmul_rn(d, d)) <= r2) lo--;
                }
                #pragma unroll
                for (int k = 0; k < 2; k++) {
                    float d = (float)(lo + 1) - y;
                    if (!(__fadd_rn(dx2, __fmul_rn(d, d)) <= r2)) lo++;
                }
                #pragma unroll
                for (int k = 0; k < 2; k++) {
                    float d = (float)(hi + 2) - y;
                    if (__fadd_rn(dx2, __fmul_rn(d, d)) <= r2) hi++;
                }
                #pragma unroll
                for (int k = 0; k < 2; k++) {
                    float d = (float)(hi + 1) - y;
                    if (!(__fadd_rn(dx2, __fmul_rn(d, d)) <= r2)) hi--;
                }
                if (lo > hi) { lo = 512; hi = -512; }
            }
            g_lohi[p0][l] = ((unsigned)(unsigned short)(short)lo)
                          | (((unsigned)(unsigned short)(short)hi) << 16);
        }
    }

    grid_barrier();   // barrier 0: all prologues staged

    // =============== B1: dynamic (phosphene, strip) task loop ===============
    for (;;) {
        if (l == 0) s_task[sub] = atomicAdd(&g_task_ctr, 1u);
        GBAR(sub);                              // also end-of-prev-task fence
        const unsigned tsk = s_task[sub];
        if (tsk >= NTASKS) break;

        const int p = (int)(tsk >> 1);
        const int s = (int)(tsk & 1u);

        const int4 ga = g_geoA[p];
        const int4 gb = g_geoB[p];
        const int oy0 = ga.x, ox0 = ga.y, cLo = ga.z, tw = ga.w;
        const int ow = gb.x, oh = gb.y;
        const bool interior = (gb.z != 0);
        const float scale = __int_as_float(gb.w);

        const int row0  = oy0 + s * STRIP_H;
        const int nrows = min(oh - s * STRIP_H, STRIP_H);   // may be <= 0

        // Copy this phosphene's metadata into our half's smem (1 ld/thread).
        if (l < 2 * H + 1)                 sw [sub][l]       = g_w [p][l];
        else if (l >= 32 && l < 32 + 22)   scw[sub][l - 32]  = g_cw[p][l - 32];
        else if (l >= 64 && l < 64 + tw)   slh[sub][l - 64]  = g_lohi[p][l - 64];
        GBAR(sub);

        if (nrows > 0) {
            const float* cwp = scw[sub];
            // Vertical: prefix-sum interval differences, O(1)/point.
            const int pts_v = nrows * tw;                   // <= 1872
            const unsigned recip_v = (1u << 22) / (unsigned)tw + 1u;
            for (int idx = l; idx < pts_v; idx += 512) {
                int i   = (int)(((unsigned)idx * recip_v) >> 22);
                int c   = idx - i * tw;
                int row = row0 + i;
                unsigned u = slh[sub][c];
                int lo = (short)(u & 0xffffu);
                int hi = (short)(u >> 16);
                t[sub][i][c] = ivsum(lo - row,        hi - row,        cwp)
                             + ivsum(-hi - row,       -lo - row,       cwp)
                             + ivsum(1022 - hi - row, 1022 - lo - row, cwp);
            }
        }
        GBAR(sub);

        if (nrows > 0) {
            // Horizontal 21-tap blur (3 chains) + threshold + atomic scatter.
            const int pts_h = nrows * ow;                   // <= 1352
            const unsigned recip_h = (1u << 22) / (unsigned)ow + 1u;
            for (int idx = l; idx < pts_h; idx += 512) {
                int i   = (int)(((unsigned)idx * recip_h) >> 22);
                int j   = idx - i * ow;
                int col = ox0 + j;
                float acc;
                if (interior) {
                    const float* trow = &t[sub][i][col - cLo - H];
                    float a0 = 0.f, a1 = 0.f, a2 = 0.f;
                    #pragma unroll
                    for (int k = 0; k < 7; k++) {
                        a0 = fmaf(sw[sub][3 * k + 0], trow[3 * k + 0], a0);
                        a1 = fmaf(sw[sub][3 * k + 1], trow[3 * k + 1], a1);
                        a2 = fmaf(sw[sub][3 * k + 2], trow[3 * k + 2], a2);
                    }
                    acc = a0 + a1 + a2;
                } else {
                    float a0 = 0.f;
                    #pragma unroll
                    for (int dx = -H; dx <= H; dx++) {
                        int cc = refl(col + dx) - cLo;
                        a0 = fmaf(sw[sub][dx + H], t[sub][i][cc], a0);
                    }
                    acc = a0;
                }
                float val = acc * scale;
                if (val >= THRESH)
                    atomicAdd(&g_scratch[(row0 + i) * SIZE + col], val);
            }
        }
        // next pop's GBAR doubles as end-of-task fence
    }

    grid_barrier();   // barrier 1: all scatters complete

    // Reset task counter for next replay (ordered after all pops; made
    // visible by barrier 2's threadfence).
    if (blockIdx.x == 0 && tid == 0) g_task_ctr = 0;

    // ------- Phase C: load + clamp (keep in regs), reduce global max -------
    const int base = blockIdx.x * PX_PER_BLOCK + tid * 2;
    float2 v2 = __ldcg(reinterpret_cast<const float2*>(g_scratch + base));
    v2.x = fminf(v2.x, 1.f); v2.y = fminf(v2.y, 1.f);
    {
        float v = fmaxf(v2.x, v2.y);
        #pragma unroll
        for (int off = 16; off > 0; off >>= 1)
            v = fmaxf(v, __shfl_xor_sync(0xffffffffu, v, off));
        int lane = tid & 31, wid = tid >> 5;
        if (lane == 0) smax[wid] = v;
        __syncthreads();
        if (wid == 0) {
            v = smax[lane];
            #pragma unroll
            for (int off = 16; off > 0; off >>= 1)
                v = fmaxf(v, __shfl_xor_sync(0xffffffffu, v, off));
            if (lane == 0) atomicMax(&g_max_bits, __float_as_int(v));
        }
    }

    grid_barrier();   // barrier 2: global max final

    // ---- Phase D: normalize regs -> d_out; re-zero scratch for next run ----
    {
        float m = __int_as_float(__ldcg(&g_max_bits));
        if (m > 0.0f) { v2.x /= m; v2.y /= m; }
        *reinterpret_cast<float2*>(img + base) = v2;
        *reinterpret_cast<float2*>(g_scratch + base) = make_float2(0.f, 0.f);
    }
}

extern "C" void kernel_launch(void* const* d_in, const int* in_sizes, int n_in,
                              void* d_out, int out_size) {
    const float* phos = (const float*)d_in[0];
    const float* grid = (const float*)d_in[1];
    if (n_in >= 2 && in_sizes[0] == 3 * N_PHOS && in_sizes[1] == N_PHOS) {
        const float* tmp = phos; phos = grid; grid = tmp;
    }
    float* img = (float*)d_out;

    k_fused<<<NBLOCKS, NTHREADS>>>(phos, grid, img);
}